// round 9
// baseline (speedup 1.0000x reference)
#include <cuda_runtime.h>
#include <stdint.h>

// FSQ quantizer for LQVitModel: z [64, 6, 256, 256] fp32, levels = [8,8,8,8,6,5].
//
// tanh-squash is monotone, so the per-dim nearest-neighbor decision boundaries
// (midpoints in bounded space) map to fixed thresholds in raw z-space:
//   z_t(j) = atanh(((j+0.5)/hw - 1 + offset)/half_l) - shift
// computed ONCE per launch in double precision by a tiny init kernel
// (16 threads, one threshold each). Deterministic, graph-capturable, no
// allocation. Main kernel is a persistent grid-stride streaming pass:
// 37 fp32 compares per site, zero transcendentals, one wave (no wave-
// transition or tail-quantization cost).
//
// q reconstruction matches the reference codebooks exactly:
//   L=8: j*0.25-1   L=6: j/3.0f-1 (IEEE fp32 div = arange(6)/3)   L=5: j*0.5-1
// index = sum_c j_c * BASIS[c].
// BASIS from the reference CODE (cumprod of levels, NOT its comment):
//   [1, 8, 64, 512, 4096, 24576]   (24576 = 4096*6; the "32768" in the
//   reference's comment is wrong). Max index 122879 < 2^24: exact in fp32.
// Output: [B*6*H*W quantized fp32, B,d,H,W layout] ++ [B*H*W indices as fp32]

#define BATCH 64
#define DIMS  6
#define HW    65536            // 256*256
#define QUADS_PER_B (HW / 4)   // 16384
#define TOTAL_QUADS (BATCH * QUADS_PER_B)

// thr[0..6]  : dims 0-3 (L=8, 7 boundaries)
// thr[7..11] : dim 4    (L=6, 5 boundaries)
// thr[12..15]: dim 5    (L=5, 4 boundaries)
__device__ float g_thr[16];

__global__ void fsq_init_thresholds()
{
    int i = threadIdx.x;
    if (i >= 16) return;

    const double eps = 1e-3;
    double thr;
    if (i < 7) {
        // L = 8 (even): half_l = 7*1.001/2, offset = 0.5, shift = atanh(0.5/half_l)
        double hl = 7.0 * (1.0 + eps) * 0.5;
        double vb = (i + 0.5) / 4.0 - 1.0;               // midpoint in bounded space
        thr = atanh((vb + 0.5) / hl) - atanh(0.5 / hl);
    } else if (i < 12) {
        // L = 6 (even): half_l = 5*1.001/2, offset = 0.5
        double hl = 5.0 * (1.0 + eps) * 0.5;
        double vb = ((i - 7) + 0.5) / 3.0 - 1.0;
        thr = atanh((vb + 0.5) / hl) - atanh(0.5 / hl);
    } else {
        // L = 5 (odd): half_l = 4*1.001/2, offset = 0, shift = 0
        double hl = 4.0 * (1.0 + eps) * 0.5;
        double vb = ((i - 12) + 0.5) / 2.0 - 1.0;
        thr = atanh(vb / hl);
    }
    g_thr[i] = (float)thr;
}

__global__ __launch_bounds__(256) void fsq_kernel(
    const float* __restrict__ z,
    float* __restrict__ out_q,
    float* __restrict__ out_idx)
{
    // Thresholds to registers once per thread (L1/L2 broadcast loads).
    float t[16];
    #pragma unroll
    for (int i = 0; i < 16; i++) t[i] = g_thr[i];

    const int TBASE[DIMS] = {0, 0, 0, 0, 7, 12};
    const int TCNT [DIMS] = {7, 7, 7, 7, 5, 4};
    const int BASIS[DIMS] = {1, 8, 64, 512, 4096, 24576};   // cumprod([8,8,8,8,6])

    const int stride = gridDim.x * blockDim.x;

    for (int q = blockIdx.x * blockDim.x + threadIdx.x; q < TOTAL_QUADS; q += stride)
    {
        int b = q >> 14;               // q / QUADS_PER_B
        int r = q & (QUADS_PER_B - 1);

        size_t base = (size_t)b * DIMS * HW + (size_t)r * 4;

        // ---- Front-batch ALL channel loads: MLP = 6 independent LDG.128 ----
        float4 zv[DIMS];
        #pragma unroll
        for (int c = 0; c < DIMS; c++)
            zv[c] = *reinterpret_cast<const float4*>(z + base + (size_t)c * HW);

        int i0 = 0, i1 = 0, i2 = 0, i3 = 0;

        #pragma unroll
        for (int c = 0; c < DIMS; c++) {
            int j0 = 0, j1 = 0, j2 = 0, j3 = 0;
            #pragma unroll
            for (int k = 0; k < TCNT[c]; k++) {
                float thr = t[TBASE[c] + k];
                j0 += (zv[c].x > thr);
                j1 += (zv[c].y > thr);
                j2 += (zv[c].z > thr);
                j3 += (zv[c].w > thr);
            }

            float4 qv;
            if (c < 4) {            // L=8, step 0.25 (exact in fp32)
                qv.x = fmaf((float)j0, 0.25f, -1.0f);
                qv.y = fmaf((float)j1, 0.25f, -1.0f);
                qv.z = fmaf((float)j2, 0.25f, -1.0f);
                qv.w = fmaf((float)j3, 0.25f, -1.0f);
            } else if (c == 4) {    // L=6: IEEE fp32 div matches arange(6)/3
                qv.x = (float)j0 / 3.0f - 1.0f;
                qv.y = (float)j1 / 3.0f - 1.0f;
                qv.z = (float)j2 / 3.0f - 1.0f;
                qv.w = (float)j3 / 3.0f - 1.0f;
            } else {                // L=5, step 0.5 (exact)
                qv.x = fmaf((float)j0, 0.5f, -1.0f);
                qv.y = fmaf((float)j1, 0.5f, -1.0f);
                qv.z = fmaf((float)j2, 0.5f, -1.0f);
                qv.w = fmaf((float)j3, 0.5f, -1.0f);
            }

            *reinterpret_cast<float4*>(out_q + base + (size_t)c * HW) = qv;

            i0 += j0 * BASIS[c];
            i1 += j1 * BASIS[c];
            i2 += j2 * BASIS[c];
            i3 += j3 * BASIS[c];
        }

        float4 iv;
        iv.x = (float)i0;            // indices <= 122879 < 2^24: exact in fp32
        iv.y = (float)i1;
        iv.z = (float)i2;
        iv.w = (float)i3;
        *reinterpret_cast<float4*>(out_idx + (size_t)b * HW + (size_t)r * 4) = iv;
    }
}

extern "C" void kernel_launch(void* const* d_in, const int* in_sizes, int n_in,
                              void* d_out, int out_size)
{
    const float* z = (const float*)d_in[0];
    float* out = (float*)d_out;
    float* out_q = out;                                   // B*6*H*W quantized values
    float* out_idx = out + (size_t)BATCH * DIMS * HW;     // B*H*W indices (as fp32)

    fsq_init_thresholds<<<1, 16>>>();                     // same stream -> ordered

    // Persistent single-wave launch: ~4 CTAs/SM at ~60 regs, 148 SMs.
    const int threads = 256;
    const int blocks = 148 * 4;                           // 592
    fsq_kernel<<<blocks, threads>>>(z, out_q, out_idx);
}

// round 10
// speedup vs baseline: 1.0223x; 1.0223x over previous
#include <cuda_runtime.h>
#include <stdint.h>

// FSQ quantizer for LQVitModel: z [64, 6, 256, 256] fp32, levels = [8,8,8,8,6,5].
//
// tanh-squash is monotone, so per-dim nearest-neighbor decision boundaries map
// to fixed thresholds in raw z-space:
//   z_t(j) = atanh(((j+0.5)/hw - 1 + offset)/half_l) - atanh(offset/half_l)
// Each CTA computes all 16 thresholds in DOUBLE precision at startup (threads
// 0-15, one atanh chain each, ~1-2us fully overlapped across the grid) into
// shared memory -- no separate init kernel, no extra graph node.
// Main loop: persistent grid-stride streaming pass, 37 fp32 compares/site,
// zero transcendentals in the hot path.
//
// q reconstruction matches the reference codebooks exactly:
//   L=8: j*0.25-1   L=6: j/3.0f-1 (IEEE fp32 div = arange(6)/3)   L=5: j*0.5-1
// index = sum_c j_c * BASIS[c], BASIS = cumprod-based [1,8,64,512,4096,24576]
// (from the reference CODE; its "32768" comment is wrong). Max index
// 122879 < 2^24: exact in fp32.
// Output: [B*6*H*W quantized fp32, B,d,H,W layout] ++ [B*H*W indices as fp32]

#define BATCH 64
#define DIMS  6
#define HW    65536            // 256*256
#define QUADS_PER_B (HW / 4)   // 16384
#define TOTAL_QUADS (BATCH * QUADS_PER_B)

__global__ __launch_bounds__(256) void fsq_kernel(
    const float* __restrict__ z,
    float* __restrict__ out_q,
    float* __restrict__ out_idx)
{
    // thr[0..6]: dims 0-3 (L=8) | thr[7..11]: dim 4 (L=6) | thr[12..15]: dim 5 (L=5)
    __shared__ float s_thr[16];

    if (threadIdx.x < 16) {
        int i = threadIdx.x;
        const double eps = 1e-3;
        double thr;
        if (i < 7) {
            // L=8 (even): half_l = 7*1.001/2, offset = 0.5
            double hl = 7.0 * (1.0 + eps) * 0.5;
            double vb = (i + 0.5) / 4.0 - 1.0;           // midpoint in bounded space
            thr = atanh((vb + 0.5) / hl) - atanh(0.5 / hl);
        } else if (i < 12) {
            // L=6 (even): half_l = 5*1.001/2, offset = 0.5
            double hl = 5.0 * (1.0 + eps) * 0.5;
            double vb = ((i - 7) + 0.5) / 3.0 - 1.0;
            thr = atanh((vb + 0.5) / hl) - atanh(0.5 / hl);
        } else {
            // L=5 (odd): half_l = 4*1.001/2, offset = 0, shift = 0
            double hl = 4.0 * (1.0 + eps) * 0.5;
            double vb = ((i - 12) + 0.5) / 2.0 - 1.0;
            thr = atanh(vb / hl);
        }
        s_thr[i] = (float)thr;
    }
    __syncthreads();

    // Thresholds to registers (LDS once per thread).
    float t[16];
    #pragma unroll
    for (int i = 0; i < 16; i++) t[i] = s_thr[i];

    const int TBASE[DIMS] = {0, 0, 0, 0, 7, 12};
    const int TCNT [DIMS] = {7, 7, 7, 7, 5, 4};
    const int BASIS[DIMS] = {1, 8, 64, 512, 4096, 24576};   // cumprod([8,8,8,8,6])

    const int stride = gridDim.x * blockDim.x;

    for (int q = blockIdx.x * blockDim.x + threadIdx.x; q < TOTAL_QUADS; q += stride)
    {
        int b = q >> 14;               // q / QUADS_PER_B
        int r = q & (QUADS_PER_B - 1);

        size_t base = (size_t)b * DIMS * HW + (size_t)r * 4;

        // ---- Front-batch ALL channel loads: MLP = 6 independent LDG.128 ----
        float4 zv[DIMS];
        #pragma unroll
        for (int c = 0; c < DIMS; c++)
            zv[c] = *reinterpret_cast<const float4*>(z + base + (size_t)c * HW);

        int i0 = 0, i1 = 0, i2 = 0, i3 = 0;

        #pragma unroll
        for (int c = 0; c < DIMS; c++) {
            int j0 = 0, j1 = 0, j2 = 0, j3 = 0;
            #pragma unroll
            for (int k = 0; k < TCNT[c]; k++) {
                float thr = t[TBASE[c] + k];
                j0 += (zv[c].x > thr);
                j1 += (zv[c].y > thr);
                j2 += (zv[c].z > thr);
                j3 += (zv[c].w > thr);
            }

            float4 qv;
            if (c < 4) {            // L=8, step 0.25 (exact in fp32)
                qv.x = fmaf((float)j0, 0.25f, -1.0f);
                qv.y = fmaf((float)j1, 0.25f, -1.0f);
                qv.z = fmaf((float)j2, 0.25f, -1.0f);
                qv.w = fmaf((float)j3, 0.25f, -1.0f);
            } else if (c == 4) {    // L=6: IEEE fp32 div matches arange(6)/3
                qv.x = (float)j0 / 3.0f - 1.0f;
                qv.y = (float)j1 / 3.0f - 1.0f;
                qv.z = (float)j2 / 3.0f - 1.0f;
                qv.w = (float)j3 / 3.0f - 1.0f;
            } else {                // L=5, step 0.5 (exact)
                qv.x = fmaf((float)j0, 0.5f, -1.0f);
                qv.y = fmaf((float)j1, 0.5f, -1.0f);
                qv.z = fmaf((float)j2, 0.5f, -1.0f);
                qv.w = fmaf((float)j3, 0.5f, -1.0f);
            }

            *reinterpret_cast<float4*>(out_q + base + (size_t)c * HW) = qv;

            i0 += j0 * BASIS[c];
            i1 += j1 * BASIS[c];
            i2 += j2 * BASIS[c];
            i3 += j3 * BASIS[c];
        }

        float4 iv;
        iv.x = (float)i0;            // indices <= 122879 < 2^24: exact in fp32
        iv.y = (float)i1;
        iv.z = (float)i2;
        iv.w = (float)i3;
        *reinterpret_cast<float4*>(out_idx + (size_t)b * HW + (size_t)r * 4) = iv;
    }
}

extern "C" void kernel_launch(void* const* d_in, const int* in_sizes, int n_in,
                              void* d_out, int out_size)
{
    const float* z = (const float*)d_in[0];
    float* out = (float*)d_out;
    float* out_q = out;                                   // B*6*H*W quantized values
    float* out_idx = out + (size_t)BATCH * DIMS * HW;     // B*H*W indices (as fp32)

    // Persistent single-wave launch: 5 CTAs/SM at 44 regs (5*256*44 = 56320
    // < 64K RF), 148 SMs -> 740 blocks.
    const int threads = 256;
    const int blocks = 148 * 5;                           // 740
    fsq_kernel<<<blocks, threads>>>(z, out_q, out_idx);
}

// round 17
// speedup vs baseline: 1.1716x; 1.1461x over previous
#include <cuda_runtime.h>
#include <stdint.h>

// FSQ quantizer for LQVitModel: z [64, 6, 256, 256] fp32, levels = [8,8,8,8,6,5].
//
// tanh-squash is monotone, so per-dim nearest-neighbor decision boundaries map
// to fixed thresholds in raw z-space:
//   z_t(j) = atanh(((j+0.5)/hw - 1 + offset)/half_l) - atanh(offset/half_l)
// Thresholds are evaluated AT COMPILE TIME via __host__ __device__ constexpr
// double-precision atanh Taylor series (args <= 0.4, 80 terms -> ~1e-15,
// identical to the runtime-DP values validated in round 9). Declared as a
// LOCAL constexpr array in the kernel (namespace-scope constexpr host vars
// are not visible in device code without --expt-relaxed-constexpr). All
// accesses use unrolled constant indices -> SASS immediates: no init kernel,
// no in-kernel DP preamble (measured +12us in round 10), no register array.
//
// Main kernel: persistent grid-stride streaming pass, 37 fp32 compares/site,
// zero transcendentals. Plain __launch_bounds__(256) -- no min-blocks clamp,
// so ptxas keeps its natural ~40 regs (no spills); 1036-block grid (7*148)
// adapts: 7 CTAs/SM -> one wave, 6 CTAs/SM -> one wave + 15% tail.
//
// q reconstruction matches the reference codebooks exactly:
//   L=8: j*0.25-1   L=6: j/3.0f-1   L=5: j*0.5-1
// index = sum_c j_c * BASIS[c], BASIS = [1,8,64,512,4096,24576] (cumprod from
// the reference CODE; its "32768" comment is wrong). Max index 122879 < 2^24.
// Output: [B*6*H*W quantized fp32, B,d,H,W layout] ++ [B*H*W indices as fp32]

#define BATCH 64
#define DIMS  6
#define HW    65536            // 256*256
#define QUADS_PER_B (HW / 4)   // 16384
#define TOTAL_QUADS (BATCH * QUADS_PER_B)

#define NBLOCKS (148 * 7)      // 1036
#define NTHREADS 256

// ---- compile-time double-precision atanh (|x| <= 0.4: series converges) ----
__host__ __device__ constexpr double catanh(double x) {
    double s = 0.0, t = x;
    const double x2 = x * x;
    for (int k = 0; k < 80; ++k) { s += t / (2.0 * k + 1.0); t *= x2; }
    return s;
}
__host__ __device__ constexpr float thr8(int i) {   // dims 0-3, L=8
    const double hl = 7.0 * 1.001 / 2.0;            // half_l; offset 0.5
    return (float)(catanh(((i + 0.5) / 4.0 - 0.5) / hl) - catanh(0.5 / hl));
}
__host__ __device__ constexpr float thr6(int i) {   // dim 4, L=6
    const double hl = 5.0 * 1.001 / 2.0;            // half_l; offset 0.5
    return (float)(catanh(((i + 0.5) / 3.0 - 0.5) / hl) - catanh(0.5 / hl));
}
__host__ __device__ constexpr float thr5(int i) {   // dim 5, L=5
    const double hl = 4.0 * 1.001 / 2.0;            // half_l; offset 0
    return (float)(catanh(((i + 0.5) / 2.0 - 1.0) / hl));
}

__global__ __launch_bounds__(NTHREADS) void fsq_kernel(
    const float* __restrict__ z,
    float* __restrict__ out_q,
    float* __restrict__ out_idx)
{
    // Local constexpr: initializers are compile-time; constant-index accesses
    // below fold to SASS immediates.
    // [0..6]: dims 0-3 | [7..11]: dim 4 | [12..15]: dim 5
    constexpr float THR[16] = {
        thr8(0), thr8(1), thr8(2), thr8(3), thr8(4), thr8(5), thr8(6),
        thr6(0), thr6(1), thr6(2), thr6(3), thr6(4),
        thr5(0), thr5(1), thr5(2), thr5(3)
    };

    const int TBASE[DIMS] = {0, 0, 0, 0, 7, 12};
    const int TCNT [DIMS] = {7, 7, 7, 7, 5, 4};
    const int BASIS[DIMS] = {1, 8, 64, 512, 4096, 24576};   // cumprod([8,8,8,8,6])

    const int stride = NBLOCKS * NTHREADS;

    for (int q = blockIdx.x * NTHREADS + threadIdx.x; q < TOTAL_QUADS; q += stride)
    {
        const int b = q >> 14;               // q / QUADS_PER_B
        const int r = q & (QUADS_PER_B - 1);

        const size_t base = (size_t)b * DIMS * HW + (size_t)r * 4;

        // ---- Front-batch ALL channel loads: 6 independent LDG.128 ----
        float4 zv[DIMS];
        #pragma unroll
        for (int c = 0; c < DIMS; c++)
            zv[c] = *reinterpret_cast<const float4*>(z + base + (size_t)c * HW);

        int i0 = 0, i1 = 0, i2 = 0, i3 = 0;

        #pragma unroll
        for (int c = 0; c < DIMS; c++) {
            int j0 = 0, j1 = 0, j2 = 0, j3 = 0;
            #pragma unroll
            for (int k = 0; k < TCNT[c]; k++) {
                const float thr = THR[TBASE[c] + k];   // compile-time constant
                j0 += (zv[c].x > thr);
                j1 += (zv[c].y > thr);
                j2 += (zv[c].z > thr);
                j3 += (zv[c].w > thr);
            }

            float4 qv;
            if (c < 4) {            // L=8, step 0.25 (exact in fp32)
                qv.x = fmaf((float)j0, 0.25f, -1.0f);
                qv.y = fmaf((float)j1, 0.25f, -1.0f);
                qv.z = fmaf((float)j2, 0.25f, -1.0f);
                qv.w = fmaf((float)j3, 0.25f, -1.0f);
            } else if (c == 4) {    // L=6: fp32 division matches arange(6)/3
                qv.x = (float)j0 / 3.0f - 1.0f;
                qv.y = (float)j1 / 3.0f - 1.0f;
                qv.z = (float)j2 / 3.0f - 1.0f;
                qv.w = (float)j3 / 3.0f - 1.0f;
            } else {                // L=5, step 0.5 (exact)
                qv.x = fmaf((float)j0, 0.5f, -1.0f);
                qv.y = fmaf((float)j1, 0.5f, -1.0f);
                qv.z = fmaf((float)j2, 0.5f, -1.0f);
                qv.w = fmaf((float)j3, 0.5f, -1.0f);
            }

            *reinterpret_cast<float4*>(out_q + base + (size_t)c * HW) = qv;

            i0 += j0 * BASIS[c];
            i1 += j1 * BASIS[c];
            i2 += j2 * BASIS[c];
            i3 += j3 * BASIS[c];
        }

        float4 iv;
        iv.x = (float)i0;            // indices <= 122879 < 2^24: exact in fp32
        iv.y = (float)i1;
        iv.z = (float)i2;
        iv.w = (float)i3;
        *reinterpret_cast<float4*>(out_idx + (size_t)b * HW + (size_t)r * 4) = iv;
    }
}

extern "C" void kernel_launch(void* const* d_in, const int* in_sizes, int n_in,
                              void* d_out, int out_size)
{
    const float* z = (const float*)d_in[0];
    float* out = (float*)d_out;
    float* out_q = out;                                   // B*6*H*W quantized values
    float* out_idx = out + (size_t)BATCH * DIMS * HW;     // B*H*W indices (as fp32)

    fsq_kernel<<<NBLOCKS, NTHREADS>>>(z, out_q, out_idx);
}